// round 15
// baseline (speedup 1.0000x reference)
#include <cuda_runtime.h>
#include <cuda_bf16.h>
#include <stdint.h>
#include <math.h>

// ---------------- problem constants ----------------
constexpr int L    = 110592;
constexpr int C    = 192;
constexpr int C3   = 576;
constexpr int HID  = 768;
constexpr int NTOK = 2304;
constexpr int NH   = 6;
constexpr int DH   = 1536;
constexpr int SROW = 27648;          // 48*576
constexpr int KOFF = 9216;
constexpr int VOFF = 18432;
constexpr long long SHEAD = (long long)NTOK * NTOK;
constexpr float SCALE = 0.17677669529663687f;

// ---------------- scratch (16B+ aligned for cp.async / float4) ----------------
__device__ __align__(256) __nv_bfloat16 g_lnxb[(long long)L * C];
__device__ __align__(256) __nv_bfloat16 g_qkvb[(long long)L * C3];
__device__ __align__(256) __nv_bfloat16 g_pb  [(long long)NH * SHEAD];   // S then P (in-place)
__device__ __align__(256) __nv_bfloat16 g_oab [(long long)L * C];
__device__ __align__(256) float         g_x1  [(long long)L * C];
__device__ __align__(256) __nv_bfloat16 g_mlpb[(long long)L * HID];
__device__ __align__(256) __nv_bfloat16 g_wq[C3 * C];
__device__ __align__(256) __nv_bfloat16 g_wp[C * C];
__device__ __align__(256) __nv_bfloat16 g_w1[HID * C];
__device__ __align__(256) __nv_bfloat16 g_w2[C * HID];

__device__ __forceinline__ uint32_t smem_u32(const void* p) {
    uint32_t a;
    asm("{ .reg .u64 t; cvta.to.shared.u64 t, %1; cvt.u32.u64 %0, t; }" : "=r"(a) : "l"(p));
    return a;
}

// ---------------- LayerNorm (fp32 in, bf16 out) ----------------
__global__ void __launch_bounds__(256) ln_kernel(
    const float* __restrict__ x, const float* __restrict__ g,
    const float* __restrict__ b, __nv_bfloat16* __restrict__ y)
{
    int warp = (blockIdx.x * blockDim.x + threadIdx.x) >> 5;
    int lane = threadIdx.x & 31;
    if (warp >= L) return;
    const float* xr = x + (size_t)warp * C;
    float v[6]; float s = 0.f, s2 = 0.f;
#pragma unroll
    for (int i = 0; i < 6; i++) {
        v[i] = xr[lane + 32 * i];
        s += v[i]; s2 += v[i] * v[i];
    }
#pragma unroll
    for (int o = 16; o; o >>= 1) {
        s  += __shfl_xor_sync(0xffffffffu, s,  o);
        s2 += __shfl_xor_sync(0xffffffffu, s2, o);
    }
    float m   = s  * (1.f / C);
    float var = s2 * (1.f / C) - m * m;
    float inv = rsqrtf(var + 1e-5f);
    __nv_bfloat16* yr = y + (size_t)warp * C;
#pragma unroll
    for (int i = 0; i < 6; i++) {
        int c = lane + 32 * i;
        yr[c] = __float2bfloat16((v[i] - m) * inv * g[c] + b[c]);
    }
}

// ---------------- softmax over 2304, bf16 in-place ----------------
__global__ void __launch_bounds__(256) softmax_kernel(__nv_bfloat16* __restrict__ P)
{
    __nv_bfloat16* p = P + (size_t)blockIdx.x * NTOK;
    int t = threadIdx.x;
    float v[9];
    float mx = -3.4e38f;
#pragma unroll
    for (int i = 0; i < 9; i++) { v[i] = __bfloat162float(p[t + 256 * i]); mx = fmaxf(mx, v[i]); }
    __shared__ float red[8];
#pragma unroll
    for (int off = 16; off; off >>= 1) mx = fmaxf(mx, __shfl_xor_sync(0xffffffffu, mx, off));
    if ((t & 31) == 0) red[t >> 5] = mx;
    __syncthreads();
    float rmax = fmaxf(fmaxf(fmaxf(red[0], red[1]), fmaxf(red[2], red[3])),
                       fmaxf(fmaxf(red[4], red[5]), fmaxf(red[6], red[7])));
    float s = 0.f;
#pragma unroll
    for (int i = 0; i < 9; i++) { v[i] = expf(v[i] - rmax); s += v[i]; }
#pragma unroll
    for (int off = 16; off; off >>= 1) s += __shfl_xor_sync(0xffffffffu, s, off);
    __syncthreads();
    if ((t & 31) == 0) red[t >> 5] = s;
    __syncthreads();
    float rs = red[0] + red[1] + red[2] + red[3] + red[4] + red[5] + red[6] + red[7];
    float inv = 1.f / rs;
#pragma unroll
    for (int i = 0; i < 9; i++) p[t + 256 * i] = __float2bfloat16(v[i] * inv);
}

// ---------------- fp32 -> bf16 convert, 4 arrays in one launch ----------------
__global__ void f2b4_kernel(const float* s0, __nv_bfloat16* d0, int n0,
                            const float* s1, __nv_bfloat16* d1, int n1,
                            const float* s2, __nv_bfloat16* d2, int n2,
                            const float* s3, __nv_bfloat16* d3, int n3)
{
    int i = blockIdx.x * 256 + threadIdx.x;
    const float* s; __nv_bfloat16* d; int n;
    switch (blockIdx.y) {
        case 0: s = s0; d = d0; n = n0; break;
        case 1: s = s1; d = d1; n = n1; break;
        case 2: s = s2; d = d2; n = n2; break;
        default: s = s3; d = d3; n = n3; break;
    }
    if (i < n) d[i] = __float2bfloat16(s[i]);
}

// ---------------- mma.sync bf16 GEMM ----------------
// BTR=0: B stored N x K (K contiguous, ldb = row stride)  -> non-trans ldmatrix
// BTR=1: B stored K x N (N contiguous, ldb = k-row stride) -> trans ldmatrix
//        (sBz and bn are COLUMN shifts in elements)
// EPI: 0 = plain bf16 out (S scores)
//      1 = PV scatter bf16: (n,h,j) -> outh[n*9216 + h*1536 + j]
//      2 = bias + resid -> fp32 out
//      3 = bias + gelu -> bf16 out
//      4 = bias + q-row-scale -> bf16 out
template<int BN, int EPI, int BTR>
__global__ void __launch_bounds__(256, 2) gemm_mma(
    const __nv_bfloat16* __restrict__ A, int lda, long long sAz,
    const __nv_bfloat16* __restrict__ B, int ldb, long long sBz,
    const float* __restrict__ bias, const float* __restrict__ resid,
    float* __restrict__ outf, __nv_bfloat16* __restrict__ outh,
    int ldc, long long sCz, int K)
{
    constexpr int BM = 128, BK = 64;
    constexpr int WARPS_M = (BN == 128) ? 2 : 4;
    constexpr int WTM = BM / WARPS_M;            // 64 or 32
    constexpr int WTN = BN / (8 / WARPS_M);      // 32
    constexpr int MT = WTM / 16;                 // 4 or 2
    constexpr int NT = WTN / 8;                  // 4
    constexpr int ABYTES = BM * 128;             // 16384
    constexpr int BBYTES = BN * 128;             // same total either layout
    constexpr int STAGE = ABYTES + BBYTES;
    constexpr int BROWB = BN * 2;                // BTR row bytes
    constexpr int BCH = BROWB / 16;              // BTR chunks per row

    extern __shared__ char smem[];

    const int tid = threadIdx.x;
    const int lane = tid & 31, wid = tid >> 5;
    const int wy = wid % WARPS_M, wx = wid / WARPS_M;

    const int bm = blockIdx.y * BM, bn = blockIdx.x * BN;
    A += blockIdx.z * sAz + (size_t)bm * lda;
    if (BTR) B += blockIdx.z * sBz + bn;                    // column shift
    else     B += blockIdx.z * sBz + (size_t)bn * ldb;      // row shift

    auto stage = [&](int t, int bsel) {
        const __nv_bfloat16* Ak = A + t * BK;
        uint32_t ab = smem_u32(smem + bsel * STAGE);
        uint32_t bb = ab + ABYTES;
#pragma unroll
        for (int i = 0; i < 4; i++) {
            int idx = tid + i * 256;
            int r = idx >> 3, c = idx & 7;
            uint32_t dst = ab + r * 128 + ((c ^ (r & 7)) << 4);
            const void* src = Ak + (size_t)r * lda + c * 8;
            asm volatile("cp.async.cg.shared.global [%0], [%1], 16;" :: "r"(dst), "l"(src));
        }
        if (!BTR) {
            const __nv_bfloat16* Bk = B + t * BK;
#pragma unroll
            for (int i = 0; i < BN / 32; i++) {
                int idx = tid + i * 256;
                int r = idx >> 3, c = idx & 7;
                uint32_t dst = bb + r * 128 + ((c ^ (r & 7)) << 4);
                const void* src = Bk + (size_t)r * ldb + c * 8;
                asm volatile("cp.async.cg.shared.global [%0], [%1], 16;" :: "r"(dst), "l"(src));
            }
        } else {
            const __nv_bfloat16* Bk = B + (size_t)t * BK * ldb;
#pragma unroll
            for (int i = 0; i < (BK * BCH) / 256; i++) {
                int idx = tid + i * 256;
                int r = idx / BCH, c = idx % BCH;
                uint32_t dst = bb + r * BROWB + ((c ^ (r & 7)) << 4);
                const void* src = Bk + (size_t)r * ldb + c * 8;
                asm volatile("cp.async.cg.shared.global [%0], [%1], 16;" :: "r"(dst), "l"(src));
            }
        }
        asm volatile("cp.async.commit_group;");
    };

    float acc[MT][NT][4];
#pragma unroll
    for (int i = 0; i < MT; i++)
#pragma unroll
        for (int j = 0; j < NT; j++)
#pragma unroll
            for (int q = 0; q < 4; q++) acc[i][j][q] = 0.f;

    const int T = K / BK;
    stage(0, 0);
    if (T > 1) stage(1, 1);

    const int r16 = lane & 15, ch = lane >> 4;

    // double-buffered fragments (breaks the LDSM->MMA WAR chain across ks steps)
    uint32_t af[2][MT][4];
    uint32_t bf[2][NT][2];

    for (int t = 0; t < T; t++) {
        if (t + 1 < T) { asm volatile("cp.async.wait_group 1;" ::: "memory"); }
        else           { asm volatile("cp.async.wait_group 0;" ::: "memory"); }
        __syncthreads();
        if (t + 2 < T) stage(t + 2, (t + 2) % 3);

        int b = t % 3;
        uint32_t sb    = smem_u32(smem + b * STAGE);
        uint32_t abase = sb + (wy * WTM) * 128;
        uint32_t braw  = sb + ABYTES;
        uint32_t bbase = braw + (wx * WTN) * 128;   // non-BTR only

        auto lf = [&](int ks, int buf) {
            const int kc = 2 * ks + ch;   // 16B-chunk index along K (A / non-trans B)
#pragma unroll
            for (int i = 0; i < MT; i++) {
                int row = i * 16 + r16;
                uint32_t addr = abase + row * 128 + ((kc ^ (row & 7)) << 4);
                asm volatile("ldmatrix.sync.aligned.m8n8.x4.shared.b16 {%0,%1,%2,%3}, [%4];"
                             : "=r"(af[buf][i][0]), "=r"(af[buf][i][1]),
                               "=r"(af[buf][i][2]), "=r"(af[buf][i][3])
                             : "r"(addr));
            }
            if (!BTR) {
#pragma unroll
                for (int j = 0; j < NT; j += 2) {
                    int rowb = j * 8 + r16;
                    uint32_t addr = bbase + rowb * 128 + ((kc ^ (rowb & 7)) << 4);
                    uint32_t t0, t1, t2, t3;
                    asm volatile("ldmatrix.sync.aligned.m8n8.x4.shared.b16 {%0,%1,%2,%3}, [%4];"
                                 : "=r"(t0), "=r"(t1), "=r"(t2), "=r"(t3) : "r"(addr));
                    bf[buf][j][0] = t0; bf[buf][j][1] = t2;
                    bf[buf][j + 1][0] = t1; bf[buf][j + 1][1] = t3;
                }
            } else {
                // B tile stored K x N: rows = k, cols = n. trans-ldmatrix yields row.col B frag.
                int krow = ks * 16 + r16;   // lanes 0-7: k octet 0 (b0), 8-15: octet 1 (b1)
#pragma unroll
                for (int j = 0; j < NT; j += 2) {
                    int cbase = wx * (WTN / 8) + j + ch;   // n-octet chunk
                    uint32_t addr = braw + krow * BROWB + ((cbase ^ (krow & 7)) << 4);
                    uint32_t t0, t1, t2, t3;
                    asm volatile("ldmatrix.sync.aligned.m8n8.x4.trans.shared.b16 {%0,%1,%2,%3}, [%4];"
                                 : "=r"(t0), "=r"(t1), "=r"(t2), "=r"(t3) : "r"(addr));
                    bf[buf][j][0] = t0; bf[buf][j][1] = t1;
                    bf[buf][j + 1][0] = t2; bf[buf][j + 1][1] = t3;
                }
            }
        };

        lf(0, 0);
#pragma unroll
        for (int ks = 0; ks < 4; ks++) {
            const int cur = ks & 1;
            if (ks < 3) lf(ks + 1, cur ^ 1);   // prefetch next frags into alternate buffer
#pragma unroll
            for (int i = 0; i < MT; i++)
#pragma unroll
                for (int j = 0; j < NT; j++) {
                    asm volatile(
                        "mma.sync.aligned.m16n8k16.row.col.f32.bf16.bf16.f32 "
                        "{%0,%1,%2,%3}, {%4,%5,%6,%7}, {%8,%9}, {%0,%1,%2,%3};"
                        : "+f"(acc[i][j][0]), "+f"(acc[i][j][1]),
                          "+f"(acc[i][j][2]), "+f"(acc[i][j][3])
                        : "r"(af[cur][i][0]), "r"(af[cur][i][1]),
                          "r"(af[cur][i][2]), "r"(af[cur][i][3]),
                          "r"(bf[cur][j][0]), "r"(bf[cur][j][1]));
                }
        }
    }

    // ---------------- epilogue ----------------
    const int gid = lane >> 2, tig = lane & 3;
#pragma unroll
    for (int i = 0; i < MT; i++) {
#pragma unroll
        for (int half = 0; half < 2; half++) {
            const size_t row = (size_t)(bm + wy * WTM + i * 16 + gid + half * 8);
            const float sc = (EPI == 4) ? (((int)(row % 48) < 16) ? SCALE : 1.0f) : 1.0f;
#pragma unroll
            for (int j = 0; j < NT; j++) {
                const int col = bn + wx * WTN + j * 8 + tig * 2;
                float c0 = acc[i][j][half * 2 + 0];
                float c1 = acc[i][j][half * 2 + 1];
                if (EPI == 0) {
                    *(__nv_bfloat162*)(outh + blockIdx.z * sCz + row * ldc + col) =
                        __floats2bfloat162_rn(c0, c1);
                } else if (EPI == 1) {
                    *(__nv_bfloat162*)(outh + row * 9216 + (size_t)blockIdx.z * 1536 + col) =
                        __floats2bfloat162_rn(c0, c1);
                } else if (EPI == 2) {
                    float2 bb = *(const float2*)(bias + col);
                    float2 rr = *(const float2*)(resid + row * ldc + col);
                    float2 o = { c0 + bb.x + rr.x, c1 + bb.y + rr.y };
                    *(float2*)(outf + row * ldc + col) = o;
                } else if (EPI == 3) {
                    float2 bb = *(const float2*)(bias + col);
                    float a0 = c0 + bb.x, a1 = c1 + bb.y;
                    a0 *= normcdff(a0);
                    a1 *= normcdff(a1);
                    *(__nv_bfloat162*)(outh + row * ldc + col) = __floats2bfloat162_rn(a0, a1);
                } else if (EPI == 4) {
                    float2 bb = *(const float2*)(bias + col);
                    *(__nv_bfloat162*)(outh + row * ldc + col) =
                        __floats2bfloat162_rn((c0 + bb.x) * sc, (c1 + bb.y) * sc);
                }
            }
        }
    }
}

// ---------------- launcher ----------------
extern "C" void kernel_launch(void* const* d_in, const int* in_sizes, int n_in,
                              void* d_out, int out_size)
{
    const float* x      = (const float*)d_in[0];
    const float* n1g    = (const float*)d_in[1];
    const float* n1b    = (const float*)d_in[2];
    const float* qkv_w  = (const float*)d_in[3];
    const float* qkv_b  = (const float*)d_in[4];
    const float* proj_w = (const float*)d_in[5];
    const float* proj_b = (const float*)d_in[6];
    const float* n2g    = (const float*)d_in[7];
    const float* n2b    = (const float*)d_in[8];
    const float* fc1_w  = (const float*)d_in[9];
    const float* fc1_b  = (const float*)d_in[10];
    const float* fc2_w  = (const float*)d_in[11];
    const float* fc2_b  = (const float*)d_in[12];
    float* out = (float*)d_out;

    __nv_bfloat16 *lnxb, *qkvb, *pb, *oab, *mlpb, *wq, *wp, *w1, *w2;
    float *x1;
    cudaGetSymbolAddress((void**)&lnxb, g_lnxb);
    cudaGetSymbolAddress((void**)&qkvb, g_qkvb);
    cudaGetSymbolAddress((void**)&pb,   g_pb);
    cudaGetSymbolAddress((void**)&oab,  g_oab);
    cudaGetSymbolAddress((void**)&x1,   g_x1);
    cudaGetSymbolAddress((void**)&mlpb, g_mlpb);
    cudaGetSymbolAddress((void**)&wq,   g_wq);
    cudaGetSymbolAddress((void**)&wp,   g_wp);
    cudaGetSymbolAddress((void**)&w1,   g_w1);
    cudaGetSymbolAddress((void**)&w2,   g_w2);

    constexpr int SM128 = 98304;   // 3*(16K A + 16K B)
    constexpr int SM64  = 73728;   // 3*(16K A + 8K B)
    cudaFuncSetAttribute(gemm_mma<128, 0, 0>, cudaFuncAttributeMaxDynamicSharedMemorySize, SM128);
    cudaFuncSetAttribute(gemm_mma<128, 1, 1>, cudaFuncAttributeMaxDynamicSharedMemorySize, SM128);
    cudaFuncSetAttribute(gemm_mma<64,  2, 0>, cudaFuncAttributeMaxDynamicSharedMemorySize, SM64);
    cudaFuncSetAttribute(gemm_mma<128, 3, 0>, cudaFuncAttributeMaxDynamicSharedMemorySize, SM128);
    cudaFuncSetAttribute(gemm_mma<64,  4, 0>, cudaFuncAttributeMaxDynamicSharedMemorySize, SM64);

    // weight conversions, one launch
    f2b4_kernel<<<dim3((HID * C + 255) / 256, 4), 256>>>(
        qkv_w, wq, C3 * C, proj_w, wp, C * C, fc1_w, w1, HID * C, fc2_w, w2, C * HID);

    // 1) LN1 -> bf16
    ln_kernel<<<L * 32 / 256, 256>>>(x, n1g, n1b, lnxb);

    // 2) QKV + bias + q-row-scale -> bf16
    gemm_mma<64, 4, 0><<<dim3(C3 / 64, L / 128, 1), 256, SM64>>>(
        lnxb, C, 0, wq, C, 0, qkv_b, nullptr, nullptr, qkvb, C3, 0, C);

    // 3) S = Qs @ K^T per head -> bf16 (into pb)
    gemm_mma<128, 0, 0><<<dim3(NTOK / 128, NTOK / 128, NH), 256, SM128>>>(
        qkvb, SROW, DH, qkvb + KOFF, SROW, DH, nullptr, nullptr,
        nullptr, pb, NTOK, SHEAD, DH);

    // 4) softmax in-place on pb
    softmax_kernel<<<NH * NTOK, 256>>>(pb);

    // 5) O = P @ V (B = V in K x N layout, trans-ldmatrix), scatter bf16
    gemm_mma<128, 1, 1><<<dim3(DH / 128, NTOK / 128, NH), 256, SM128>>>(
        pb, NTOK, SHEAD, qkvb + VOFF, SROW, DH, nullptr, nullptr,
        nullptr, oab, 0, 0, NTOK);

    // 6) x1 = x + O @ proj_w^T + proj_b (fp32)
    gemm_mma<64, 2, 0><<<dim3(C / 64, L / 128, 1), 256, SM64>>>(
        oab, C, 0, wp, C, 0, proj_b, x, x1, nullptr, C, 0, C);

    // 7) LN2 -> bf16
    ln_kernel<<<L * 32 / 256, 256>>>(x1, n2g, n2b, lnxb);

    // 8) fc1 + gelu -> bf16
    gemm_mma<128, 3, 0><<<dim3(HID / 128, L / 128, 1), 256, SM128>>>(
        lnxb, C, 0, w1, C, 0, fc1_b, nullptr, nullptr, mlpb, HID, 0, C);

    // 9) out = x1 + mlp @ fc2_w^T + fc2_b (fp32)
    gemm_mma<64, 2, 0><<<dim3(C / 64, L / 128, 1), 256, SM64>>>(
        mlpb, HID, 0, w2, HID, 0, fc2_b, x1, out, nullptr, C, 0, HID);
}

// round 16
// speedup vs baseline: 1.0056x; 1.0056x over previous
#include <cuda_runtime.h>
#include <cuda_bf16.h>
#include <stdint.h>
#include <math.h>

// ---------------- problem constants ----------------
constexpr int L    = 110592;
constexpr int C    = 192;
constexpr int C3   = 576;
constexpr int HID  = 768;
constexpr int NTOK = 2304;
constexpr int NH   = 6;
constexpr int DH   = 1536;
constexpr int SROW = 27648;          // 48*576
constexpr int KOFF = 9216;
constexpr int VOFF = 18432;
constexpr long long SHEAD = (long long)NTOK * NTOK;
constexpr float SCALE = 0.17677669529663687f;

// ---------------- scratch (16B+ aligned for cp.async / float4) ----------------
__device__ __align__(256) __nv_bfloat16 g_lnxb[(long long)L * C];
__device__ __align__(256) __nv_bfloat16 g_qkvb[(long long)L * C3];
__device__ __align__(256) __nv_bfloat16 g_pb  [(long long)NH * SHEAD];   // S then P (in-place)
__device__ __align__(256) __nv_bfloat16 g_oab [(long long)L * C];
__device__ __align__(256) float         g_x1  [(long long)L * C];
__device__ __align__(256) __nv_bfloat16 g_mlpb[(long long)L * HID];
__device__ __align__(256) __nv_bfloat16 g_wq[C3 * C];
__device__ __align__(256) __nv_bfloat16 g_wp[C * C];
__device__ __align__(256) __nv_bfloat16 g_w1[HID * C];
__device__ __align__(256) __nv_bfloat16 g_w2[C * HID];

__device__ __forceinline__ uint32_t smem_u32(const void* p) {
    uint32_t a;
    asm("{ .reg .u64 t; cvta.to.shared.u64 t, %1; cvt.u32.u64 %0, t; }" : "=r"(a) : "l"(p));
    return a;
}

// ---------------- LayerNorm (fp32 in, bf16 out) ----------------
__global__ void __launch_bounds__(256) ln_kernel(
    const float* __restrict__ x, const float* __restrict__ g,
    const float* __restrict__ b, __nv_bfloat16* __restrict__ y)
{
    int warp = (blockIdx.x * blockDim.x + threadIdx.x) >> 5;
    int lane = threadIdx.x & 31;
    if (warp >= L) return;
    const float* xr = x + (size_t)warp * C;
    float v[6]; float s = 0.f, s2 = 0.f;
#pragma unroll
    for (int i = 0; i < 6; i++) {
        v[i] = xr[lane + 32 * i];
        s += v[i]; s2 += v[i] * v[i];
    }
#pragma unroll
    for (int o = 16; o; o >>= 1) {
        s  += __shfl_xor_sync(0xffffffffu, s,  o);
        s2 += __shfl_xor_sync(0xffffffffu, s2, o);
    }
    float m   = s  * (1.f / C);
    float var = s2 * (1.f / C) - m * m;
    float inv = rsqrtf(var + 1e-5f);
    __nv_bfloat16* yr = y + (size_t)warp * C;
#pragma unroll
    for (int i = 0; i < 6; i++) {
        int c = lane + 32 * i;
        yr[c] = __float2bfloat16((v[i] - m) * inv * g[c] + b[c]);
    }
}

// ---------------- softmax over 2304, bf16 in-place ----------------
__global__ void __launch_bounds__(256) softmax_kernel(__nv_bfloat16* __restrict__ P)
{
    __nv_bfloat16* p = P + (size_t)blockIdx.x * NTOK;
    int t = threadIdx.x;
    float v[9];
    float mx = -3.4e38f;
#pragma unroll
    for (int i = 0; i < 9; i++) { v[i] = __bfloat162float(p[t + 256 * i]); mx = fmaxf(mx, v[i]); }
    __shared__ float red[8];
#pragma unroll
    for (int off = 16; off; off >>= 1) mx = fmaxf(mx, __shfl_xor_sync(0xffffffffu, mx, off));
    if ((t & 31) == 0) red[t >> 5] = mx;
    __syncthreads();
    float rmax = fmaxf(fmaxf(fmaxf(red[0], red[1]), fmaxf(red[2], red[3])),
                       fmaxf(fmaxf(red[4], red[5]), fmaxf(red[6], red[7])));
    float s = 0.f;
#pragma unroll
    for (int i = 0; i < 9; i++) { v[i] = expf(v[i] - rmax); s += v[i]; }
#pragma unroll
    for (int off = 16; off; off >>= 1) s += __shfl_xor_sync(0xffffffffu, s, off);
    __syncthreads();
    if ((t & 31) == 0) red[t >> 5] = s;
    __syncthreads();
    float rs = red[0] + red[1] + red[2] + red[3] + red[4] + red[5] + red[6] + red[7];
    float inv = 1.f / rs;
#pragma unroll
    for (int i = 0; i < 9; i++) p[t + 256 * i] = __float2bfloat16(v[i] * inv);
}

// ---------------- fp32 -> bf16 convert, 4 arrays in one launch ----------------
__global__ void f2b4_kernel(const float* s0, __nv_bfloat16* d0, int n0,
                            const float* s1, __nv_bfloat16* d1, int n1,
                            const float* s2, __nv_bfloat16* d2, int n2,
                            const float* s3, __nv_bfloat16* d3, int n3)
{
    int i = blockIdx.x * 256 + threadIdx.x;
    const float* s; __nv_bfloat16* d; int n;
    switch (blockIdx.y) {
        case 0: s = s0; d = d0; n = n0; break;
        case 1: s = s1; d = d1; n = n1; break;
        case 2: s = s2; d = d2; n = n2; break;
        default: s = s3; d = d3; n = n3; break;
    }
    if (i < n) d[i] = __float2bfloat16(s[i]);
}

// ---------------- mma.sync bf16 GEMM ----------------
// BTR=0: B stored N x K (K contiguous, ldb = row stride)  -> non-trans ldmatrix
// BTR=1: B stored K x N (N contiguous, ldb = k-row stride) -> trans ldmatrix
//        (sBz and bn are COLUMN shifts in elements)
// EPI: 0 = plain bf16 out (S scores)
//      1 = PV scatter bf16: (n,h,j) -> outh[n*9216 + h*1536 + j]
//      2 = bias + resid -> fp32 out
//      3 = bias + gelu -> bf16 out
//      4 = bias + q-row-scale -> bf16 out
template<int BN, int EPI, int BTR>
__global__ void __launch_bounds__(256, 2) gemm_mma(
    const __nv_bfloat16* __restrict__ A, int lda, long long sAz,
    const __nv_bfloat16* __restrict__ B, int ldb, long long sBz,
    const float* __restrict__ bias, const float* __restrict__ resid,
    float* __restrict__ outf, __nv_bfloat16* __restrict__ outh,
    int ldc, long long sCz, int K)
{
    constexpr int BM = 128, BK = 64;
    constexpr int WARPS_M = (BN == 128) ? 2 : 4;
    constexpr int WTM = BM / WARPS_M;            // 64 or 32
    constexpr int WTN = BN / (8 / WARPS_M);      // 32
    constexpr int MT = WTM / 16;                 // 4 or 2
    constexpr int NT = WTN / 8;                  // 4
    constexpr int ABYTES = BM * 128;             // 16384
    constexpr int BBYTES = BN * 128;             // same total either layout
    constexpr int STAGE = ABYTES + BBYTES;
    constexpr int BROWB = BN * 2;                // BTR row bytes
    constexpr int BCH = BROWB / 16;              // BTR chunks per row

    extern __shared__ char smem[];

    const int tid = threadIdx.x;
    const int lane = tid & 31, wid = tid >> 5;
    const int wy = wid % WARPS_M, wx = wid / WARPS_M;

    const int bm = blockIdx.y * BM, bn = blockIdx.x * BN;
    A += blockIdx.z * sAz + (size_t)bm * lda;
    if (BTR) B += blockIdx.z * sBz + bn;                    // column shift
    else     B += blockIdx.z * sBz + (size_t)bn * ldb;      // row shift

    auto stage = [&](int t, int bsel) {
        const __nv_bfloat16* Ak = A + t * BK;
        uint32_t ab = smem_u32(smem + bsel * STAGE);
        uint32_t bb = ab + ABYTES;
#pragma unroll
        for (int i = 0; i < 4; i++) {
            int idx = tid + i * 256;
            int r = idx >> 3, c = idx & 7;
            uint32_t dst = ab + r * 128 + ((c ^ (r & 7)) << 4);
            const void* src = Ak + (size_t)r * lda + c * 8;
            asm volatile("cp.async.cg.shared.global [%0], [%1], 16;" :: "r"(dst), "l"(src));
        }
        if (!BTR) {
            const __nv_bfloat16* Bk = B + t * BK;
#pragma unroll
            for (int i = 0; i < BN / 32; i++) {
                int idx = tid + i * 256;
                int r = idx >> 3, c = idx & 7;
                uint32_t dst = bb + r * 128 + ((c ^ (r & 7)) << 4);
                const void* src = Bk + (size_t)r * ldb + c * 8;
                asm volatile("cp.async.cg.shared.global [%0], [%1], 16;" :: "r"(dst), "l"(src));
            }
        } else {
            const __nv_bfloat16* Bk = B + (size_t)t * BK * ldb;
#pragma unroll
            for (int i = 0; i < (BK * BCH) / 256; i++) {
                int idx = tid + i * 256;
                int r = idx / BCH, c = idx % BCH;
                uint32_t dst = bb + r * BROWB + ((c ^ (r & 7)) << 4);
                const void* src = Bk + (size_t)r * ldb + c * 8;
                asm volatile("cp.async.cg.shared.global [%0], [%1], 16;" :: "r"(dst), "l"(src));
            }
        }
        asm volatile("cp.async.commit_group;");
    };

    float acc[MT][NT][4];
#pragma unroll
    for (int i = 0; i < MT; i++)
#pragma unroll
        for (int j = 0; j < NT; j++)
#pragma unroll
            for (int q = 0; q < 4; q++) acc[i][j][q] = 0.f;

    const int T = K / BK;
    stage(0, 0);
    if (T > 1) stage(1, 1);

    for (int t = 0; t < T; t++) {
        if (t + 1 < T) { asm volatile("cp.async.wait_group 1;" ::: "memory"); }
        else           { asm volatile("cp.async.wait_group 0;" ::: "memory"); }
        __syncthreads();
        if (t + 2 < T) stage(t + 2, (t + 2) % 3);

        int b = t % 3;
        uint32_t abase = smem_u32(smem + b * STAGE) + (wy * WTM) * 128;
        uint32_t braw  = smem_u32(smem + b * STAGE) + ABYTES;
        uint32_t bbase = braw + (wx * WTN) * 128;   // non-BTR only
        const int r16 = lane & 15, ch = lane >> 4;
#pragma unroll
        for (int ks = 0; ks < 4; ks++) {
            // per-warp rotated ks order: all 4 steps of a staged tile are
            // independent, so stagger warps to spread LDSM bursts / MMA stalls.
            const int ksr = (ks + wid) & 3;
            const int kc = 2 * ksr + ch;   // 16B-chunk index along K (A / non-trans B)
            uint32_t af[MT][4];
#pragma unroll
            for (int i = 0; i < MT; i++) {
                int row = i * 16 + r16;
                uint32_t addr = abase + row * 128 + ((kc ^ (row & 7)) << 4);
                asm volatile("ldmatrix.sync.aligned.m8n8.x4.shared.b16 {%0,%1,%2,%3}, [%4];"
                             : "=r"(af[i][0]), "=r"(af[i][1]), "=r"(af[i][2]), "=r"(af[i][3])
                             : "r"(addr));
            }
            uint32_t bf[NT][2];
            if (!BTR) {
#pragma unroll
                for (int j = 0; j < NT; j += 2) {
                    int rowb = j * 8 + r16;
                    uint32_t addr = bbase + rowb * 128 + ((kc ^ (rowb & 7)) << 4);
                    uint32_t t0, t1, t2, t3;
                    asm volatile("ldmatrix.sync.aligned.m8n8.x4.shared.b16 {%0,%1,%2,%3}, [%4];"
                                 : "=r"(t0), "=r"(t1), "=r"(t2), "=r"(t3) : "r"(addr));
                    bf[j][0] = t0; bf[j][1] = t2; bf[j + 1][0] = t1; bf[j + 1][1] = t3;
                }
            } else {
                // B tile stored K x N: rows = k, cols = n. trans-ldmatrix yields row.col B frag.
                int krow = ksr * 16 + r16;   // lanes 0-7: k octet 0 (b0), 8-15: octet 1 (b1)
#pragma unroll
                for (int j = 0; j < NT; j += 2) {
                    int cbase = wx * (WTN / 8) + j + ch;   // n-octet chunk
                    uint32_t addr = braw + krow * BROWB + ((cbase ^ (krow & 7)) << 4);
                    uint32_t t0, t1, t2, t3;
                    asm volatile("ldmatrix.sync.aligned.m8n8.x4.trans.shared.b16 {%0,%1,%2,%3}, [%4];"
                                 : "=r"(t0), "=r"(t1), "=r"(t2), "=r"(t3) : "r"(addr));
                    bf[j][0] = t0; bf[j][1] = t1; bf[j + 1][0] = t2; bf[j + 1][1] = t3;
                }
            }
#pragma unroll
            for (int i = 0; i < MT; i++)
#pragma unroll
                for (int j = 0; j < NT; j++) {
                    asm volatile(
                        "mma.sync.aligned.m16n8k16.row.col.f32.bf16.bf16.f32 "
                        "{%0,%1,%2,%3}, {%4,%5,%6,%7}, {%8,%9}, {%0,%1,%2,%3};"
                        : "+f"(acc[i][j][0]), "+f"(acc[i][j][1]),
                          "+f"(acc[i][j][2]), "+f"(acc[i][j][3])
                        : "r"(af[i][0]), "r"(af[i][1]), "r"(af[i][2]), "r"(af[i][3]),
                          "r"(bf[j][0]), "r"(bf[j][1]));
                }
        }
    }

    // ---------------- epilogue ----------------
    const int gid = lane >> 2, tig = lane & 3;
#pragma unroll
    for (int i = 0; i < MT; i++) {
#pragma unroll
        for (int half = 0; half < 2; half++) {
            const size_t row = (size_t)(bm + wy * WTM + i * 16 + gid + half * 8);
            const float sc = (EPI == 4) ? (((int)(row % 48) < 16) ? SCALE : 1.0f) : 1.0f;
#pragma unroll
            for (int j = 0; j < NT; j++) {
                const int col = bn + wx * WTN + j * 8 + tig * 2;
                float c0 = acc[i][j][half * 2 + 0];
                float c1 = acc[i][j][half * 2 + 1];
                if (EPI == 0) {
                    *(__nv_bfloat162*)(outh + blockIdx.z * sCz + row * ldc + col) =
                        __floats2bfloat162_rn(c0, c1);
                } else if (EPI == 1) {
                    *(__nv_bfloat162*)(outh + row * 9216 + (size_t)blockIdx.z * 1536 + col) =
                        __floats2bfloat162_rn(c0, c1);
                } else if (EPI == 2) {
                    float2 bb = *(const float2*)(bias + col);
                    float2 rr = *(const float2*)(resid + row * ldc + col);
                    float2 o = { c0 + bb.x + rr.x, c1 + bb.y + rr.y };
                    *(float2*)(outf + row * ldc + col) = o;
                } else if (EPI == 3) {
                    float2 bb = *(const float2*)(bias + col);
                    float a0 = c0 + bb.x, a1 = c1 + bb.y;
                    a0 *= normcdff(a0);
                    a1 *= normcdff(a1);
                    *(__nv_bfloat162*)(outh + row * ldc + col) = __floats2bfloat162_rn(a0, a1);
                } else if (EPI == 4) {
                    float2 bb = *(const float2*)(bias + col);
                    *(__nv_bfloat162*)(outh + row * ldc + col) =
                        __floats2bfloat162_rn((c0 + bb.x) * sc, (c1 + bb.y) * sc);
                }
            }
        }
    }
}

// ---------------- launcher ----------------
extern "C" void kernel_launch(void* const* d_in, const int* in_sizes, int n_in,
                              void* d_out, int out_size)
{
    const float* x      = (const float*)d_in[0];
    const float* n1g    = (const float*)d_in[1];
    const float* n1b    = (const float*)d_in[2];
    const float* qkv_w  = (const float*)d_in[3];
    const float* qkv_b  = (const float*)d_in[4];
    const float* proj_w = (const float*)d_in[5];
    const float* proj_b = (const float*)d_in[6];
    const float* n2g    = (const float*)d_in[7];
    const float* n2b    = (const float*)d_in[8];
    const float* fc1_w  = (const float*)d_in[9];
    const float* fc1_b  = (const float*)d_in[10];
    const float* fc2_w  = (const float*)d_in[11];
    const float* fc2_b  = (const float*)d_in[12];
    float* out = (float*)d_out;

    __nv_bfloat16 *lnxb, *qkvb, *pb, *oab, *mlpb, *wq, *wp, *w1, *w2;
    float *x1;
    cudaGetSymbolAddress((void**)&lnxb, g_lnxb);
    cudaGetSymbolAddress((void**)&qkvb, g_qkvb);
    cudaGetSymbolAddress((void**)&pb,   g_pb);
    cudaGetSymbolAddress((void**)&oab,  g_oab);
    cudaGetSymbolAddress((void**)&x1,   g_x1);
    cudaGetSymbolAddress((void**)&mlpb, g_mlpb);
    cudaGetSymbolAddress((void**)&wq,   g_wq);
    cudaGetSymbolAddress((void**)&wp,   g_wp);
    cudaGetSymbolAddress((void**)&w1,   g_w1);
    cudaGetSymbolAddress((void**)&w2,   g_w2);

    constexpr int SM128 = 98304;   // 3*(16K A + 16K B)
    constexpr int SM64  = 73728;   // 3*(16K A + 8K B)
    cudaFuncSetAttribute(gemm_mma<128, 0, 0>, cudaFuncAttributeMaxDynamicSharedMemorySize, SM128);
    cudaFuncSetAttribute(gemm_mma<128, 1, 1>, cudaFuncAttributeMaxDynamicSharedMemorySize, SM128);
    cudaFuncSetAttribute(gemm_mma<64,  2, 0>, cudaFuncAttributeMaxDynamicSharedMemorySize, SM64);
    cudaFuncSetAttribute(gemm_mma<128, 3, 0>, cudaFuncAttributeMaxDynamicSharedMemorySize, SM128);
    cudaFuncSetAttribute(gemm_mma<64,  4, 0>, cudaFuncAttributeMaxDynamicSharedMemorySize, SM64);

    // weight conversions, one launch
    f2b4_kernel<<<dim3((HID * C + 255) / 256, 4), 256>>>(
        qkv_w, wq, C3 * C, proj_w, wp, C * C, fc1_w, w1, HID * C, fc2_w, w2, C * HID);

    // 1) LN1 -> bf16
    ln_kernel<<<L * 32 / 256, 256>>>(x, n1g, n1b, lnxb);

    // 2) QKV + bias + q-row-scale -> bf16
    gemm_mma<64, 4, 0><<<dim3(C3 / 64, L / 128, 1), 256, SM64>>>(
        lnxb, C, 0, wq, C, 0, qkv_b, nullptr, nullptr, qkvb, C3, 0, C);

    // 3) S = Qs @ K^T per head -> bf16 (into pb)
    gemm_mma<128, 0, 0><<<dim3(NTOK / 128, NTOK / 128, NH), 256, SM128>>>(
        qkvb, SROW, DH, qkvb + KOFF, SROW, DH, nullptr, nullptr,
        nullptr, pb, NTOK, SHEAD, DH);

    // 4) softmax in-place on pb
    softmax_kernel<<<NH * NTOK, 256>>>(pb);

    // 5) O = P @ V (B = V in K x N layout, trans-ldmatrix), scatter bf16
    gemm_mma<128, 1, 1><<<dim3(DH / 128, NTOK / 128, NH), 256, SM128>>>(
        pb, NTOK, SHEAD, qkvb + VOFF, SROW, DH, nullptr, nullptr,
        nullptr, oab, 0, 0, NTOK);

    // 6) x1 = x + O @ proj_w^T + proj_b (fp32)
    gemm_mma<64, 2, 0><<<dim3(C / 64, L / 128, 1), 256, SM64>>>(
        oab, C, 0, wp, C, 0, proj_b, x, x1, nullptr, C, 0, C);

    // 7) LN2 -> bf16
    ln_kernel<<<L * 32 / 256, 256>>>(x1, n2g, n2b, lnxb);

    // 8) fc1 + gelu -> bf16
    gemm_mma<128, 3, 0><<<dim3(HID / 128, L / 128, 1), 256, SM128>>>(
        lnxb, C, 0, w1, C, 0, fc1_b, nullptr, nullptr, mlpb, HID, 0, C);

    // 9) out = x1 + mlp @ fc2_w^T + fc2_b (fp32)
    gemm_mma<64, 2, 0><<<dim3(C / 64, L / 128, 1), 256, SM64>>>(
        mlpb, HID, 0, w2, HID, 0, fc2_b, x1, out, nullptr, C, 0, HID);
}

// round 17
// speedup vs baseline: 1.0217x; 1.0160x over previous
#include <cuda_runtime.h>
#include <cuda_bf16.h>
#include <stdint.h>
#include <math.h>

// ---------------- problem constants ----------------
constexpr int L    = 110592;
constexpr int C    = 192;
constexpr int C3   = 576;
constexpr int HID  = 768;
constexpr int NTOK = 2304;
constexpr int NH   = 6;
constexpr int DH   = 1536;
constexpr int SROW = 27648;          // 48*576
constexpr int KOFF = 9216;
constexpr int VOFF = 18432;
constexpr long long SHEAD = (long long)NTOK * NTOK;
constexpr float SCALE = 0.17677669529663687f;

// ---------------- scratch (16B+ aligned for cp.async / float4) ----------------
__device__ __align__(256) __nv_bfloat16 g_lnxb[(long long)L * C];
__device__ __align__(256) __nv_bfloat16 g_qkvb[(long long)L * C3];
__device__ __align__(256) __nv_bfloat16 g_pb  [(long long)NH * SHEAD];   // S then P (in-place)
__device__ __align__(256) __nv_bfloat16 g_oab [(long long)L * C];
__device__ __align__(256) float         g_x1  [(long long)L * C];
__device__ __align__(256) __nv_bfloat16 g_mlpb[(long long)L * HID];
__device__ __align__(256) __nv_bfloat16 g_wq[C3 * C];
__device__ __align__(256) __nv_bfloat16 g_wp[C * C];
__device__ __align__(256) __nv_bfloat16 g_w1[HID * C];
__device__ __align__(256) __nv_bfloat16 g_w2[C * HID];

__device__ __forceinline__ uint32_t smem_u32(const void* p) {
    uint32_t a;
    asm("{ .reg .u64 t; cvta.to.shared.u64 t, %1; cvt.u32.u64 %0, t; }" : "=r"(a) : "l"(p));
    return a;
}

// ---------------- LayerNorm (fp32 in, bf16 out) ----------------
__global__ void __launch_bounds__(256) ln_kernel(
    const float* __restrict__ x, const float* __restrict__ g,
    const float* __restrict__ b, __nv_bfloat16* __restrict__ y)
{
    int warp = (blockIdx.x * blockDim.x + threadIdx.x) >> 5;
    int lane = threadIdx.x & 31;
    if (warp >= L) return;
    const float* xr = x + (size_t)warp * C;
    float v[6]; float s = 0.f, s2 = 0.f;
#pragma unroll
    for (int i = 0; i < 6; i++) {
        v[i] = xr[lane + 32 * i];
        s += v[i]; s2 += v[i] * v[i];
    }
#pragma unroll
    for (int o = 16; o; o >>= 1) {
        s  += __shfl_xor_sync(0xffffffffu, s,  o);
        s2 += __shfl_xor_sync(0xffffffffu, s2, o);
    }
    float m   = s  * (1.f / C);
    float var = s2 * (1.f / C) - m * m;
    float inv = rsqrtf(var + 1e-5f);
    __nv_bfloat16* yr = y + (size_t)warp * C;
#pragma unroll
    for (int i = 0; i < 6; i++) {
        int c = lane + 32 * i;
        yr[c] = __float2bfloat16((v[i] - m) * inv * g[c] + b[c]);
    }
}

// ---------------- softmax over 2304, bf16 in-place ----------------
__global__ void __launch_bounds__(256) softmax_kernel(__nv_bfloat16* __restrict__ P)
{
    __nv_bfloat16* p = P + (size_t)blockIdx.x * NTOK;
    int t = threadIdx.x;
    float v[9];
    float mx = -3.4e38f;
#pragma unroll
    for (int i = 0; i < 9; i++) { v[i] = __bfloat162float(p[t + 256 * i]); mx = fmaxf(mx, v[i]); }
    __shared__ float red[8];
#pragma unroll
    for (int off = 16; off; off >>= 1) mx = fmaxf(mx, __shfl_xor_sync(0xffffffffu, mx, off));
    if ((t & 31) == 0) red[t >> 5] = mx;
    __syncthreads();
    float rmax = fmaxf(fmaxf(fmaxf(red[0], red[1]), fmaxf(red[2], red[3])),
                       fmaxf(fmaxf(red[4], red[5]), fmaxf(red[6], red[7])));
    float s = 0.f;
#pragma unroll
    for (int i = 0; i < 9; i++) { v[i] = expf(v[i] - rmax); s += v[i]; }
#pragma unroll
    for (int off = 16; off; off >>= 1) s += __shfl_xor_sync(0xffffffffu, s, off);
    __syncthreads();
    if ((t & 31) == 0) red[t >> 5] = s;
    __syncthreads();
    float rs = red[0] + red[1] + red[2] + red[3] + red[4] + red[5] + red[6] + red[7];
    float inv = 1.f / rs;
#pragma unroll
    for (int i = 0; i < 9; i++) p[t + 256 * i] = __float2bfloat16(v[i] * inv);
}

// ---------------- fp32 -> bf16 convert, 4 arrays in one launch ----------------
__global__ void f2b4_kernel(const float* s0, __nv_bfloat16* d0, int n0,
                            const float* s1, __nv_bfloat16* d1, int n1,
                            const float* s2, __nv_bfloat16* d2, int n2,
                            const float* s3, __nv_bfloat16* d3, int n3)
{
    int i = blockIdx.x * 256 + threadIdx.x;
    const float* s; __nv_bfloat16* d; int n;
    switch (blockIdx.y) {
        case 0: s = s0; d = d0; n = n0; break;
        case 1: s = s1; d = d1; n = n1; break;
        case 2: s = s2; d = d2; n = n2; break;
        default: s = s3; d = d3; n = n3; break;
    }
    if (i < n) d[i] = __float2bfloat16(s[i]);
}

// ---------------- mma.sync bf16 GEMM ----------------
// BM=128: 3-stage pipeline. BM=256: 2-stage pipeline, warp grid 4x2 (warp tile 64x32).
// BTR=0: B stored N x K (K contiguous)  -> non-trans ldmatrix
// BTR=1: B stored K x N (N contiguous)  -> trans ldmatrix (sBz/bn are column shifts)
// EPI: 0 = plain bf16 out (S scores)
//      1 = PV scatter bf16: (n,h,j) -> outh[n*9216 + h*1536 + j]
//      2 = bias + resid -> fp32 out
//      3 = bias + gelu -> bf16 out
//      4 = bias + q-row-scale -> bf16 out
template<int BM, int BN, int EPI, int BTR>
__global__ void __launch_bounds__(256, 2) gemm_mma(
    const __nv_bfloat16* __restrict__ A, int lda, long long sAz,
    const __nv_bfloat16* __restrict__ B, int ldb, long long sBz,
    const float* __restrict__ bias, const float* __restrict__ resid,
    float* __restrict__ outf, __nv_bfloat16* __restrict__ outh,
    int ldc, long long sCz, int K)
{
    constexpr int BK = 64;
    constexpr int WARPS_M = (BM == 256) ? 4 : ((BN == 128) ? 2 : 4);
    constexpr int WTM = BM / WARPS_M;            // 64 / 64 / 32
    constexpr int WTN = BN / (8 / WARPS_M);      // 32 always
    constexpr int MT = WTM / 16;                 // 4 or 2
    constexpr int NT = WTN / 8;                  // 4
    constexpr int ABYTES = BM * 128;
    constexpr int BBYTES = BN * 128;             // same total either B layout
    constexpr int STAGE = ABYTES + BBYTES;
    constexpr int NSTAGE = (BM == 256) ? 2 : 3;
    constexpr int BROWB = BN * 2;                // BTR row bytes
    constexpr int BCH = BROWB / 16;              // BTR chunks per row

    extern __shared__ char smem[];

    const int tid = threadIdx.x;
    const int lane = tid & 31, wid = tid >> 5;
    const int wy = wid % WARPS_M, wx = wid / WARPS_M;

    const int bm = blockIdx.y * BM, bn = blockIdx.x * BN;
    A += blockIdx.z * sAz + (size_t)bm * lda;
    if (BTR) B += blockIdx.z * sBz + bn;                    // column shift
    else     B += blockIdx.z * sBz + (size_t)bn * ldb;      // row shift

    auto stage = [&](int t, int bsel) {
        const __nv_bfloat16* Ak = A + t * BK;
        uint32_t ab = smem_u32(smem + bsel * STAGE);
        uint32_t bb = ab + ABYTES;
#pragma unroll
        for (int i = 0; i < BM / 32; i++) {
            int idx = tid + i * 256;
            int r = idx >> 3, c = idx & 7;
            uint32_t dst = ab + r * 128 + ((c ^ (r & 7)) << 4);
            const void* src = Ak + (size_t)r * lda + c * 8;
            asm volatile("cp.async.cg.shared.global [%0], [%1], 16;" :: "r"(dst), "l"(src));
        }
        if (!BTR) {
            const __nv_bfloat16* Bk = B + t * BK;
#pragma unroll
            for (int i = 0; i < BN / 32; i++) {
                int idx = tid + i * 256;
                int r = idx >> 3, c = idx & 7;
                uint32_t dst = bb + r * 128 + ((c ^ (r & 7)) << 4);
                const void* src = Bk + (size_t)r * ldb + c * 8;
                asm volatile("cp.async.cg.shared.global [%0], [%1], 16;" :: "r"(dst), "l"(src));
            }
        } else {
            const __nv_bfloat16* Bk = B + (size_t)t * BK * ldb;
#pragma unroll
            for (int i = 0; i < (BK * BCH) / 256; i++) {
                int idx = tid + i * 256;
                int r = idx / BCH, c = idx % BCH;
                uint32_t dst = bb + r * BROWB + ((c ^ (r & 7)) << 4);
                const void* src = Bk + (size_t)r * ldb + c * 8;
                asm volatile("cp.async.cg.shared.global [%0], [%1], 16;" :: "r"(dst), "l"(src));
            }
        }
        asm volatile("cp.async.commit_group;");
    };

    float acc[MT][NT][4];
#pragma unroll
    for (int i = 0; i < MT; i++)
#pragma unroll
        for (int j = 0; j < NT; j++)
#pragma unroll
            for (int q = 0; q < 4; q++) acc[i][j][q] = 0.f;

    const int T = K / BK;
    stage(0, 0);
    if (NSTAGE == 3 && T > 1) stage(1, 1);

    for (int t = 0; t < T; t++) {
        if (NSTAGE == 3) {
            if (t + 1 < T) { asm volatile("cp.async.wait_group 1;" ::: "memory"); }
            else           { asm volatile("cp.async.wait_group 0;" ::: "memory"); }
            __syncthreads();
            if (t + 2 < T) stage(t + 2, (t + 2) % 3);
        } else {
            asm volatile("cp.async.wait_group 0;" ::: "memory");
            __syncthreads();
            if (t + 1 < T) stage(t + 1, (t + 1) & 1);
        }

        int b = t % NSTAGE;
        uint32_t abase = smem_u32(smem + b * STAGE) + (wy * WTM) * 128;
        uint32_t braw  = smem_u32(smem + b * STAGE) + ABYTES;
        uint32_t bbase = braw + (wx * WTN) * 128;   // non-BTR only
        const int r16 = lane & 15, ch = lane >> 4;
#pragma unroll
        for (int ks = 0; ks < 4; ks++) {
            const int kc = 2 * ks + ch;   // 16B-chunk index along K (A / non-trans B)
            uint32_t af[MT][4];
#pragma unroll
            for (int i = 0; i < MT; i++) {
                int row = i * 16 + r16;
                uint32_t addr = abase + row * 128 + ((kc ^ (row & 7)) << 4);
                asm volatile("ldmatrix.sync.aligned.m8n8.x4.shared.b16 {%0,%1,%2,%3}, [%4];"
                             : "=r"(af[i][0]), "=r"(af[i][1]), "=r"(af[i][2]), "=r"(af[i][3])
                             : "r"(addr));
            }
            uint32_t bf[NT][2];
            if (!BTR) {
#pragma unroll
                for (int j = 0; j < NT; j += 2) {
                    int rowb = j * 8 + r16;
                    uint32_t addr = bbase + rowb * 128 + ((kc ^ (rowb & 7)) << 4);
                    uint32_t t0, t1, t2, t3;
                    asm volatile("ldmatrix.sync.aligned.m8n8.x4.shared.b16 {%0,%1,%2,%3}, [%4];"
                                 : "=r"(t0), "=r"(t1), "=r"(t2), "=r"(t3) : "r"(addr));
                    bf[j][0] = t0; bf[j][1] = t2; bf[j + 1][0] = t1; bf[j + 1][1] = t3;
                }
            } else {
                // B tile stored K x N: rows = k, cols = n. trans-ldmatrix yields row.col B frag.
                int krow = ks * 16 + r16;   // lanes 0-7: k octet 0 (b0), 8-15: octet 1 (b1)
#pragma unroll
                for (int j = 0; j < NT; j += 2) {
                    int cbase = wx * (WTN / 8) + j + ch;   // n-octet chunk
                    uint32_t addr = braw + krow * BROWB + ((cbase ^ (krow & 7)) << 4);
                    uint32_t t0, t1, t2, t3;
                    asm volatile("ldmatrix.sync.aligned.m8n8.x4.trans.shared.b16 {%0,%1,%2,%3}, [%4];"
                                 : "=r"(t0), "=r"(t1), "=r"(t2), "=r"(t3) : "r"(addr));
                    bf[j][0] = t0; bf[j][1] = t1; bf[j + 1][0] = t2; bf[j + 1][1] = t3;
                }
            }
#pragma unroll
            for (int i = 0; i < MT; i++)
#pragma unroll
                for (int j = 0; j < NT; j++) {
                    asm volatile(
                        "mma.sync.aligned.m16n8k16.row.col.f32.bf16.bf16.f32 "
                        "{%0,%1,%2,%3}, {%4,%5,%6,%7}, {%8,%9}, {%0,%1,%2,%3};"
                        : "+f"(acc[i][j][0]), "+f"(acc[i][j][1]),
                          "+f"(acc[i][j][2]), "+f"(acc[i][j][3])
                        : "r"(af[i][0]), "r"(af[i][1]), "r"(af[i][2]), "r"(af[i][3]),
                          "r"(bf[j][0]), "r"(bf[j][1]));
                }
        }
    }

    // ---------------- epilogue ----------------
    const int gid = lane >> 2, tig = lane & 3;
#pragma unroll
    for (int i = 0; i < MT; i++) {
#pragma unroll
        for (int half = 0; half < 2; half++) {
            const size_t row = (size_t)(bm + wy * WTM + i * 16 + gid + half * 8);
            const float sc = (EPI == 4) ? (((int)(row % 48) < 16) ? SCALE : 1.0f) : 1.0f;
#pragma unroll
            for (int j = 0; j < NT; j++) {
                const int col = bn + wx * WTN + j * 8 + tig * 2;
                float c0 = acc[i][j][half * 2 + 0];
                float c1 = acc[i][j][half * 2 + 1];
                if (EPI == 0) {
                    *(__nv_bfloat162*)(outh + blockIdx.z * sCz + row * ldc + col) =
                        __floats2bfloat162_rn(c0, c1);
                } else if (EPI == 1) {
                    *(__nv_bfloat162*)(outh + row * 9216 + (size_t)blockIdx.z * 1536 + col) =
                        __floats2bfloat162_rn(c0, c1);
                } else if (EPI == 2) {
                    float2 bb = *(const float2*)(bias + col);
                    float2 rr = *(const float2*)(resid + row * ldc + col);
                    float2 o = { c0 + bb.x + rr.x, c1 + bb.y + rr.y };
                    *(float2*)(outf + row * ldc + col) = o;
                } else if (EPI == 3) {
                    float2 bb = *(const float2*)(bias + col);
                    float a0 = c0 + bb.x, a1 = c1 + bb.y;
                    a0 *= normcdff(a0);
                    a1 *= normcdff(a1);
                    *(__nv_bfloat162*)(outh + row * ldc + col) = __floats2bfloat162_rn(a0, a1);
                } else if (EPI == 4) {
                    float2 bb = *(const float2*)(bias + col);
                    *(__nv_bfloat162*)(outh + row * ldc + col) =
                        __floats2bfloat162_rn((c0 + bb.x) * sc, (c1 + bb.y) * sc);
                }
            }
        }
    }
}

// ---------------- launcher ----------------
extern "C" void kernel_launch(void* const* d_in, const int* in_sizes, int n_in,
                              void* d_out, int out_size)
{
    const float* x      = (const float*)d_in[0];
    const float* n1g    = (const float*)d_in[1];
    const float* n1b    = (const float*)d_in[2];
    const float* qkv_w  = (const float*)d_in[3];
    const float* qkv_b  = (const float*)d_in[4];
    const float* proj_w = (const float*)d_in[5];
    const float* proj_b = (const float*)d_in[6];
    const float* n2g    = (const float*)d_in[7];
    const float* n2b    = (const float*)d_in[8];
    const float* fc1_w  = (const float*)d_in[9];
    const float* fc1_b  = (const float*)d_in[10];
    const float* fc2_w  = (const float*)d_in[11];
    const float* fc2_b  = (const float*)d_in[12];
    float* out = (float*)d_out;

    __nv_bfloat16 *lnxb, *qkvb, *pb, *oab, *mlpb, *wq, *wp, *w1, *w2;
    float *x1;
    cudaGetSymbolAddress((void**)&lnxb, g_lnxb);
    cudaGetSymbolAddress((void**)&qkvb, g_qkvb);
    cudaGetSymbolAddress((void**)&pb,   g_pb);
    cudaGetSymbolAddress((void**)&oab,  g_oab);
    cudaGetSymbolAddress((void**)&x1,   g_x1);
    cudaGetSymbolAddress((void**)&mlpb, g_mlpb);
    cudaGetSymbolAddress((void**)&wq,   g_wq);
    cudaGetSymbolAddress((void**)&wp,   g_wp);
    cudaGetSymbolAddress((void**)&w1,   g_w1);
    cudaGetSymbolAddress((void**)&w2,   g_w2);

    constexpr int SM128 = 98304;   // 3*(16K A + 16K B)
    constexpr int SM256 = 81920;   // 2*(32K A + 8K B)
    cudaFuncSetAttribute(gemm_mma<128, 128, 0, 0>, cudaFuncAttributeMaxDynamicSharedMemorySize, SM128);
    cudaFuncSetAttribute(gemm_mma<128, 128, 1, 1>, cudaFuncAttributeMaxDynamicSharedMemorySize, SM128);
    cudaFuncSetAttribute(gemm_mma<128, 128, 3, 0>, cudaFuncAttributeMaxDynamicSharedMemorySize, SM128);
    cudaFuncSetAttribute(gemm_mma<256, 64,  2, 0>, cudaFuncAttributeMaxDynamicSharedMemorySize, SM256);
    cudaFuncSetAttribute(gemm_mma<256, 64,  4, 0>, cudaFuncAttributeMaxDynamicSharedMemorySize, SM256);

    // weight conversions, one launch
    f2b4_kernel<<<dim3((HID * C + 255) / 256, 4), 256>>>(
        qkv_w, wq, C3 * C, proj_w, wp, C * C, fc1_w, w1, HID * C, fc2_w, w2, C * HID);

    // 1) LN1 -> bf16
    ln_kernel<<<L * 32 / 256, 256>>>(x, n1g, n1b, lnxb);

    // 2) QKV + bias + q-row-scale -> bf16   (BM=256 path)
    gemm_mma<256, 64, 4, 0><<<dim3(C3 / 64, L / 256, 1), 256, SM256>>>(
        lnxb, C, 0, wq, C, 0, qkv_b, nullptr, nullptr, qkvb, C3, 0, C);

    // 3) S = Qs @ K^T per head -> bf16 (into pb)
    gemm_mma<128, 128, 0, 0><<<dim3(NTOK / 128, NTOK / 128, NH), 256, SM128>>>(
        qkvb, SROW, DH, qkvb + KOFF, SROW, DH, nullptr, nullptr,
        nullptr, pb, NTOK, SHEAD, DH);

    // 4) softmax in-place on pb
    softmax_kernel<<<NH * NTOK, 256>>>(pb);

    // 5) O = P @ V (B = V in K x N layout, trans-ldmatrix), scatter bf16
    gemm_mma<128, 128, 1, 1><<<dim3(DH / 128, NTOK / 128, NH), 256, SM128>>>(
        pb, NTOK, SHEAD, qkvb + VOFF, SROW, DH, nullptr, nullptr,
        nullptr, oab, 0, 0, NTOK);

    // 6) x1 = x + O @ proj_w^T + proj_b (fp32)   (BM=256 path)
    gemm_mma<256, 64, 2, 0><<<dim3(C / 64, L / 256, 1), 256, SM256>>>(
        oab, C, 0, wp, C, 0, proj_b, x, x1, nullptr, C, 0, C);

    // 7) LN2 -> bf16
    ln_kernel<<<L * 32 / 256, 256>>>(x1, n2g, n2b, lnxb);

    // 8) fc1 + gelu -> bf16
    gemm_mma<128, 128, 3, 0><<<dim3(HID / 128, L / 128, 1), 256, SM128>>>(
        lnxb, C, 0, w1, C, 0, fc1_b, nullptr, nullptr, mlpb, HID, 0, C);

    // 9) out = x1 + mlp @ fc2_w^T + fc2_b (fp32)   (BM=256 path)
    gemm_mma<256, 64, 2, 0><<<dim3(C / 64, L / 256, 1), 256, SM256>>>(
        mlpb, HID, 0, w2, HID, 0, fc2_b, x1, out, nullptr, C, 0, HID);
}